// round 14
// baseline (speedup 1.0000x reference)
#include <cuda_runtime.h>
#include <cuda_fp16.h>
#include <cstdint>
#include <math.h>

// SlatewiseGRU: B=128, S=64, K=10, D=256.
// Input second half is zeros => threshold mask dead, GI GEMM hoisted.
// R13: rnn as ONE 1024-thread CTA per batch (32 warps/SM, occ 50%) with a
// 64-reg/thread diet: acc 48 (warp owns 32 rows x 16 d x 3 gates), B frags
// 4 live, A via ldmatrix reloaded per gate. gi unchanged from R12.

// ---------------------------------------------------------------------------
static __device__ __forceinline__ uint32_t smem_u32(const void* p) {
    uint32_t a;
    asm("{ .reg .u64 t; cvta.to.shared.u64 t, %1; cvt.u32.u64 %0, t; }"
        : "=r"(a) : "l"(p));
    return a;
}
static __device__ __forceinline__ void cp16(uint32_t dst, const void* src) {
    asm volatile("cp.async.cg.shared.global [%0], [%1], 16;"
                 :: "r"(dst), "l"(src));
}
static __device__ __forceinline__ void cp_commit() {
    asm volatile("cp.async.commit_group;" ::: "memory");
}
static __device__ __forceinline__ void cp_wait1() {
    asm volatile("cp.async.wait_group 1;" ::: "memory");
}
static __device__ __forceinline__ void cp_wait0() {
    asm volatile("cp.async.wait_group 0;" ::: "memory");
}
static __device__ __forceinline__ void prefetch_l2(const void* p) {
    asm volatile("prefetch.global.L2 [%0];" :: "l"(p));
}
// pack two fp32 into f16x2 reg: low half = x0 (even k), high half = x1
static __device__ __forceinline__ uint32_t pack_h2(float x0, float x1) {
    uint32_t r;
    asm("cvt.rn.f16x2.f32 %0, %1, %2;" : "=r"(r) : "f"(x1), "f"(x0));
    return r;
}
// split (x0,x1) into fp16 hi pair + fp16 lo (residual) pair
static __device__ __forceinline__ uint32_t split_h2(float x0, float x1,
                                                    uint32_t& lo) {
    uint32_t hi = pack_h2(x0, x1);
    half2 h = *reinterpret_cast<half2*>(&hi);
    float2 b = __half22float2(h);
    lo = pack_h2(x0 - b.x, x1 - b.y);
    return hi;
}
// D += A(16x16) * B(16x8), fp16 inputs, fp32 accum.
static __device__ __forceinline__ void mma16816(float& d0, float& d1, float& d2,
                                                float& d3, uint32_t a0,
                                                uint32_t a1, uint32_t a2,
                                                uint32_t a3, uint32_t b0,
                                                uint32_t b1) {
    asm("mma.sync.aligned.m16n8k16.row.col.f32.f16.f16.f32 "
        "{%0,%1,%2,%3}, {%4,%5,%6,%7}, {%8,%9}, {%0,%1,%2,%3};"
        : "+f"(d0), "+f"(d1), "+f"(d2), "+f"(d3)
        : "r"(a0), "r"(a1), "r"(a2), "r"(a3), "r"(b0), "r"(b1));
}
// ldmatrix x4: four 8x8 b16 tiles; lane supplies its row address.
static __device__ __forceinline__ void ldsm_x4(uint32_t& r0, uint32_t& r1,
                                               uint32_t& r2, uint32_t& r3,
                                               uint32_t addr) {
    asm volatile("ldmatrix.sync.aligned.m8n8.x4.shared.b16 {%0,%1,%2,%3}, [%4];"
                 : "=r"(r0), "=r"(r1), "=r"(r2), "=r"(r3) : "r"(addr));
}
static __device__ __forceinline__ float fast_sig(float x) {
    return __fdividef(1.0f, 1.0f + __expf(-x));
}
static __device__ __forceinline__ float fast_tanh(float x) {
    float t = __expf(-2.0f * fabsf(x));
    float r = __fdividef(1.0f - t, 1.0f + t);
    return copysignf(r, x);
}

// Scratch (device globals: allocation-free per harness rules)
__device__ float g_GI[62914560];         // [81920][768] input gates (+biases)
__device__ uint32_t g_IPk_hi[10485760];  // [81920 rows][128 kpair] f16x2 items
__device__ uint32_t g_IPk_lo[10485760];
__device__ uint32_t g_WihPk_hi[98304];   // [128 kpair][768 j] f16x2 W_ih^T
__device__ uint32_t g_WhhPk_hi[98304];   // [128 kpair][768 j] f16x2 W_hh^T

// ---------------------------------------------------------------------------
__global__ void prep_weights(const float* __restrict__ W_ih,
                             const float* __restrict__ W_hh) {
    int idx = blockIdx.x * 256 + threadIdx.x;  // 98304 = 128 kpair x 768 j
    if (idx >= 98304) return;
    int kp = idx / 768;
    int j = idx - kp * 768;
    g_WihPk_hi[idx] = pack_h2(W_ih[(size_t)j * 512 + 2 * kp],
                              W_ih[(size_t)j * 512 + 2 * kp + 1]);
    g_WhhPk_hi[idx] = pack_h2(W_hh[(size_t)j * 256 + 2 * kp],
                              W_hh[(size_t)j * 256 + 2 * kp + 1]);
}

__global__ void prep_items(const float* __restrict__ A) {
    // 81920 rows x 128 kpairs = 10485760 pairs; 10240 blocks x 256 thr x 4
    int base = blockIdx.x * 256 + threadIdx.x;
#pragma unroll
    for (int it = 0; it < 4; it++) {
        int i = base + it * 2621440;
        float2 v = ((const float2*)A)[i];
        uint32_t lo, hi = split_h2(v.x, v.y, lo);
        g_IPk_hi[i] = hi;
        g_IPk_lo[i] = lo;
    }
}

// ---------------------------------------------------------------------------
// GI[r, j] = sum_k items[r,k] * W_ih[j,k] (+ bias), 2-term fp16 split
// ((a_hi + a_lo) @ fp16(W_ih)). Block tile 128x128, 8 warps (2m x 4n).
// K chunked by 32 (16 kpairs), cp.async double-buffered.
// Grid = (6 j-blocks, 640 r-blocks): j inner => A tiles reused from L2.
__global__ void __launch_bounds__(256, 2) gi_tc(const float* __restrict__ b_ih,
                                                const float* __restrict__ b_hh) {
    extern __shared__ uint32_t smu[];
    // A: (2p+h)*2560 : [128 m][20] (16 kpair + 4 pad)
    // B: 10240 + p*2176 : [16 kpair][136] (132+4 pad, stride 136%32==8)
    const uint32_t sbase = smem_u32(smu);
    const int tid = threadIdx.x;
    const int lane = tid & 31, w = tid >> 5;
    const int gid = lane >> 2, tidg = lane & 3;
    const int mbase = (w >> 2) * 64, nbase = (w & 3) * 32;
    const int r0 = blockIdx.y * 128, j0 = blockIdx.x * 128;

    float acc[4][4][4];
#pragma unroll
    for (int mt = 0; mt < 4; mt++)
#pragma unroll
        for (int nt = 0; nt < 4; nt++)
#pragma unroll
            for (int c = 0; c < 4; c++) acc[mt][nt][c] = 0.0f;

    auto issue = [&](int c) {
        int p = c & 1;
        uint32_t aA = sbase + (uint32_t)(2 * p * 2560) * 4;
        uint32_t aB = sbase + (uint32_t)(10240 + p * 2176) * 4;
#pragma unroll
        for (int it = 0; it < 4; it++) {
            int f = tid + it * 256;           // 1024 cp16: [h][128 m][4 k4]
            int h = f >> 9, rem = f & 511;
            int m = rem >> 2, k4 = rem & 3;
            const uint32_t* src = (h ? g_IPk_lo : g_IPk_hi) +
                                  (size_t)(r0 + m) * 128 + c * 16 + k4 * 4;
            cp16(aA + (uint32_t)(h * 2560 + m * 20 + k4 * 4) * 4, src);
        }
#pragma unroll
        for (int it = 0; it < 2; it++) {
            int f = tid + it * 256;           // 512 cp16: [16 kp][32 j4]
            int kp = f >> 5, j4 = f & 31;
            cp16(aB + (uint32_t)(kp * 136 + j4 * 4) * 4,
                 g_WihPk_hi + (size_t)(c * 16 + kp) * 768 + j0 + j4 * 4);
        }
        cp_commit();
    };

    issue(0);
    for (int c = 0; c < 8; c++) {
        if (c + 1 < 8) { issue(c + 1); cp_wait1(); } else { cp_wait0(); }
        __syncthreads();
        const uint32_t* Ah = smu + 2 * (c & 1) * 2560;
        const uint32_t* Al = Ah + 2560;
        const uint32_t* Bh = smu + 10240 + (c & 1) * 2176;
#pragma unroll
        for (int ks = 0; ks < 2; ks++) {
            const int kp0 = 8 * ks + tidg, kp1 = kp0 + 4;
            uint32_t bh[4][2];
#pragma unroll
            for (int nt = 0; nt < 4; nt++) {
                int j = nbase + 8 * nt + gid;
                bh[nt][0] = Bh[kp0 * 136 + j];
                bh[nt][1] = Bh[kp1 * 136 + j];
            }
#pragma unroll
            for (int mt = 0; mt < 4; mt++) {
                int row = mbase + 16 * mt + gid;
                uint32_t ah0 = Ah[row * 20 + kp0];
                uint32_t ah1 = Ah[(row + 8) * 20 + kp0];
                uint32_t ah2 = Ah[row * 20 + kp1];
                uint32_t ah3 = Ah[(row + 8) * 20 + kp1];
                uint32_t al0 = Al[row * 20 + kp0];
                uint32_t al1 = Al[(row + 8) * 20 + kp0];
                uint32_t al2 = Al[row * 20 + kp1];
                uint32_t al3 = Al[(row + 8) * 20 + kp1];
#pragma unroll
                for (int nt = 0; nt < 4; nt++) {
                    mma16816(acc[mt][nt][0], acc[mt][nt][1], acc[mt][nt][2],
                             acc[mt][nt][3], ah0, ah1, ah2, ah3,
                             bh[nt][0], bh[nt][1]);
                    mma16816(acc[mt][nt][0], acc[mt][nt][1], acc[mt][nt][2],
                             acc[mt][nt][3], al0, al1, al2, al3,
                             bh[nt][0], bh[nt][1]);
                }
            }
        }
        __syncthreads();  // buffer reuse guard before next issue
    }

    // epilogue: add bias, store float2s
    const bool addh = (j0 + nbase) < 512;
    float2 bias[4];
#pragma unroll
    for (int nt = 0; nt < 4; nt++) {
        int j = j0 + nbase + 8 * nt + 2 * tidg;
        float2 v = *(const float2*)(b_ih + j);
        if (addh) {
            float2 h2 = *(const float2*)(b_hh + j);
            v.x += h2.x; v.y += h2.y;
        }
        bias[nt] = v;
    }
#pragma unroll
    for (int mt = 0; mt < 4; mt++)
#pragma unroll
        for (int rh = 0; rh < 2; rh++) {
            int row = mbase + 16 * mt + 8 * rh + gid;
            float* dst = g_GI + (size_t)(r0 + row) * 768 + j0 + nbase;
#pragma unroll
            for (int nt = 0; nt < 4; nt++) {
                float2 o;
                o.x = acc[mt][nt][2 * rh] + bias[nt].x;
                o.y = acc[mt][nt][2 * rh + 1] + bias[nt].y;
                *(float2*)(dst + 8 * nt + 2 * tidg) = o;
            }
        }
}

// ---------------------------------------------------------------------------
// RNN: one CTA per batch, 1024 threads = 32 warps (occ 50%).
// Warp w: mhalf = w>>4 -> rows [32*mhalf, +32); dslice = w&15 ->
// d in [16*dslice, +16) for all 3 gates. acc = 48 floats/thread.
// h in SMEM as f16x2 hi/lo; 2-term split (h_hi + h_lo) @ fp16(W_hh).
// Weights staged per 16-kpair chunk, triple-buffered, one barrier/chunk.
__global__ void __launch_bounds__(1024) rnn_tc(const float* __restrict__ user_embs,
                                               const float* __restrict__ b_hh,
                                               const float* __restrict__ w_out,
                                               const float* __restrict__ b_out,
                                               const int* __restrict__ length,
                                               float* __restrict__ out) {
    extern __shared__ uint32_t smu[];
    uint32_t* hsm_hi = smu;            // [64][132] (128 kpair + 4 pad)
    uint32_t* hsm_lo = smu + 8448;
    // weight bufs @16896 + (c%3)*12416 : [16 kp][776]
    float* ysm = (float*)(smu + 54144);  // [64]
    const uint32_t sbase = smem_u32(smu);

    const int b = blockIdx.x;
    const int tid = threadIdx.x;
    const int lane = tid & 31, w = tid >> 5;
    const int gid = lane >> 2, tidg = lane & 3;
    const int dslice = w & 15, mhalf = w >> 4;
    const int dbase = dslice * 16;
    // ldmatrix per-lane offset within a 16-row tile pair, plus mhalf rows.
    const uint32_t lmoff =
        (uint32_t)(mhalf * 32 * 132 + (lane & 15) * 132 + ((lane >> 4) << 2)) * 4;
    const uint32_t lmb_hi = sbase + lmoff;
    const uint32_t lmb_lo = sbase + 8448 * 4 + lmoff;

    // h0 = user_embs[b, clip(len-1,0)] broadcast to 64 rows, split to f16 hi/lo
    int hidx = length[b] - 1;
    if (hidx < 0) hidx = 0;
    const float* u0 = user_embs + ((size_t)b * 64 + hidx) * 256;
    for (int i = tid; i < 64 * 128; i += 1024) {
        int row = i >> 7, kp = i & 127;
        float2 v = *(const float2*)(u0 + 2 * kp);
        uint32_t lo, hi = split_h2(v.x, v.y, lo);
        hsm_hi[row * 132 + kp] = hi;
        hsm_lo[row * 132 + kp] = lo;
    }
    const float bout = b_out[0];
    if (tid < 64) ysm[tid] = bout;

    auto issue = [&](int c) {
        int bf = c - (c / 3) * 3;  // c % 3
#pragma unroll
        for (int it = 0; it < 3; it++) {
            int f = tid + it * 1024;       // 3072 cp16: [16 kk][192 j4]
            int kk = f / 192, j4 = f - kk * 192;
            cp16(sbase + (uint32_t)(16896 + bf * 12416 + kk * 776 + j4 * 4) * 4,
                 g_WhhPk_hi + (size_t)(c * 16 + kk) * 768 + j4 * 4);
        }
        cp_commit();
    };

    float acc[2][3][2][4];

    for (int k = 0; k < 10; k++) {
        // prefetch this step's GI slab (64 rows x 768 floats) into L2
        {
            const float* gib = g_GI + ((size_t)(b * 64) * 10 + k) * 768;
            for (int i = tid; i < 1536; i += 1024) {
                int r = i / 24, l = i - r * 24;
                prefetch_l2((const char*)(gib + (size_t)r * 7680) + l * 128);
            }
        }
#pragma unroll
        for (int mt = 0; mt < 2; mt++)
#pragma unroll
            for (int g = 0; g < 3; g++)
#pragma unroll
                for (int nt = 0; nt < 2; nt++)
#pragma unroll
                    for (int c = 0; c < 4; c++) acc[mt][g][nt][c] = 0.0f;

        issue(0);
        issue(1);
        for (int c = 0; c < 8; c++) {
            if (c < 7) cp_wait1(); else cp_wait0();
            __syncthreads();   // single barrier per chunk (triple buffer)
            if (c < 6) issue(c + 2);
            const uint32_t* wb = smu + 16896 + (c - (c / 3) * 3) * 12416;
#pragma unroll
            for (int ks = 0; ks < 2; ks++) {
                const uint32_t kbyte = (uint32_t)(16 * c + 8 * ks) * 4;
                const int xr0 = (8 * ks + tidg) * 776;
                const int xr1 = (8 * ks + tidg + 4) * 776;
#pragma unroll
                for (int g = 0; g < 3; g++) {
                    // 4 live B regs for this gate's d-slice
                    const int n0 = g * 256 + dbase + gid;
                    uint32_t b0a = wb[xr0 + n0];
                    uint32_t b1a = wb[xr1 + n0];
                    uint32_t b0b = wb[xr0 + n0 + 8];
                    uint32_t b1b = wb[xr1 + n0 + 8];
#pragma unroll
                    for (int pass = 0; pass < 2; pass++) {
                        const uint32_t lmb = pass ? lmb_lo : lmb_hi;
#pragma unroll
                        for (int mt = 0; mt < 2; mt++) {
                            uint32_t a0, a1, a2, a3;
                            ldsm_x4(a0, a1, a2, a3,
                                    lmb + (uint32_t)mt * 8448 + kbyte);
                            mma16816(acc[mt][g][0][0], acc[mt][g][0][1],
                                     acc[mt][g][0][2], acc[mt][g][0][3],
                                     a0, a1, a2, a3, b0a, b1a);
                            mma16816(acc[mt][g][1][0], acc[mt][g][1][1],
                                     acc[mt][g][1][2], acc[mt][g][1][3],
                                     a0, a1, a2, a3, b0b, b1b);
                        }
                    }
                }
            }
        }
        __syncthreads();  // all h reads done before epilogue rewrites h

        // fused GRU epilogue (each (row,d) cell owned by exactly one thread)
        float2 bhn[2], wo[2];
#pragma unroll
        for (int nt = 0; nt < 2; nt++) {
            int d = dbase + 8 * nt + 2 * tidg;
            bhn[nt] = *(const float2*)(b_hh + 512 + d);
            wo[nt] = *(const float2*)(w_out + d);
        }
#pragma unroll
        for (int mt = 0; mt < 2; mt++)
#pragma unroll
            for (int rh = 0; rh < 2; rh++) {
                int row = mhalf * 32 + 16 * mt + 8 * rh + gid;
                const float* gi = g_GI + ((size_t)(b * 64 + row) * 10 + k) * 768;
                float yp = 0.0f;
#pragma unroll
                for (int nt = 0; nt < 2; nt++) {
                    int d = dbase + 8 * nt + 2 * tidg;
                    int kp = d >> 1;
                    float2 gr = *(const float2*)(gi + d);
                    float2 gz = *(const float2*)(gi + 256 + d);
                    float2 gn = *(const float2*)(gi + 512 + d);
                    uint32_t hh = hsm_hi[row * 132 + kp];
                    uint32_t hl = hsm_lo[row * 132 + kp];
                    float2 hhf = __half22float2(*reinterpret_cast<half2*>(&hh));
                    float2 hlf = __half22float2(*reinterpret_cast<half2*>(&hl));
                    float hox = hhf.x + hlf.x, hoy = hhf.y + hlf.y;
                    int c0 = rh * 2;
                    float r0v = fast_sig(gr.x + acc[mt][0][nt][c0]);
                    float r1v = fast_sig(gr.y + acc[mt][0][nt][c0 + 1]);
                    float z0v = fast_sig(gz.x + acc[mt][1][nt][c0]);
                    float z1v = fast_sig(gz.y + acc[mt][1][nt][c0 + 1]);
                    float hn0 = acc[mt][2][nt][c0] + bhn[nt].x;
                    float hn1 = acc[mt][2][nt][c0 + 1] + bhn[nt].y;
                    float n0 = fast_tanh(gn.x + r0v * hn0);
                    float n1 = fast_tanh(gn.y + r1v * hn1);
                    float h0n = (1.0f - z0v) * n0 + z0v * hox;
                    float h1n = (1.0f - z1v) * n1 + z1v * hoy;
                    uint32_t nlo, nhi = split_h2(h0n, h1n, nlo);
                    hsm_hi[row * 132 + kp] = nhi;
                    hsm_lo[row * 132 + kp] = nlo;
                    yp += h0n * wo[nt].x + h1n * wo[nt].y;
                }
                yp += __shfl_xor_sync(0xffffffffu, yp, 1);
                yp += __shfl_xor_sync(0xffffffffu, yp, 2);
                if (tidg == 0) atomicAdd(&ysm[row], yp);
            }
        __syncthreads();
        if (tid < 64) {
            out[((size_t)(b * 64) + tid) * 10 + k] = ysm[tid];
            ysm[tid] = bout;
        }
        // next step's chunk-0 barrier orders h/ysm writes vs reads
    }
}

// ---------------------------------------------------------------------------
extern "C" void kernel_launch(void* const* d_in, const int* in_sizes, int n_in,
                              void* d_out, int out_size) {
    (void)in_sizes; (void)n_in; (void)out_size;
    const float* item_embs = (const float*)d_in[0];  // [128,64,10,256]
    const float* user_embs = (const float*)d_in[1];  // [128,64,256]
    const float* W_ih      = (const float*)d_in[2];  // [768,512]
    const float* W_hh      = (const float*)d_in[3];  // [768,256]
    const float* b_ih      = (const float*)d_in[4];  // [768]
    const float* b_hh      = (const float*)d_in[5];  // [768]
    const float* w_out     = (const float*)d_in[6];  // [256]
    const float* b_out     = (const float*)d_in[7];  // scalar
    const int*   length    = (const int*)d_in[8];    // [128]
    float* out = (float*)d_out;                      // [128,64,10]

    prep_weights<<<384, 256>>>(W_ih, W_hh);
    prep_items<<<10240, 256>>>(item_embs);

    const int gi_smem = 14592 * 4;  // 58368 B
    cudaFuncSetAttribute(gi_tc, cudaFuncAttributeMaxDynamicSharedMemorySize,
                         gi_smem);
    dim3 gg(6, 640);  // j-blocks inner => A-tile L2 reuse across 6 j-blocks
    gi_tc<<<gg, 256, gi_smem>>>(b_ih, b_hh);

    const int rnn_smem = 54208 * 4;  // 216832 B
    cudaFuncSetAttribute(rnn_tc, cudaFuncAttributeMaxDynamicSharedMemorySize,
                         rnn_smem);
    rnn_tc<<<128, 1024, rnn_smem>>>(user_embs, b_hh, w_out, b_out, length, out);
}

// round 15
// speedup vs baseline: 1.4770x; 1.4770x over previous
#include <cuda_runtime.h>
#include <cuda_fp16.h>
#include <cstdint>
#include <math.h>

// SlatewiseGRU: B=128, S=64, K=10, D=256.
// Input second half is zeros => threshold mask dead, GI GEMM hoisted.
// R14: recombine best-measured components. rnn = R8 exactly (128 CTAs x 512
// thr, plain LDS A-loads, double-buffered 16-kpair chunks; 297us measured).
// gi = R12 exactly (2-term fp16 split; ~195us measured). R9/R12/R13 rnn
// restructures all regressed (smem-port / L2 walls), so no new ideas here.

// ---------------------------------------------------------------------------
static __device__ __forceinline__ uint32_t smem_u32(const void* p) {
    uint32_t a;
    asm("{ .reg .u64 t; cvta.to.shared.u64 t, %1; cvt.u32.u64 %0, t; }"
        : "=r"(a) : "l"(p));
    return a;
}
static __device__ __forceinline__ void cp16(uint32_t dst, const void* src) {
    asm volatile("cp.async.cg.shared.global [%0], [%1], 16;"
                 :: "r"(dst), "l"(src));
}
static __device__ __forceinline__ void cp_commit() {
    asm volatile("cp.async.commit_group;" ::: "memory");
}
static __device__ __forceinline__ void cp_wait1() {
    asm volatile("cp.async.wait_group 1;" ::: "memory");
}
static __device__ __forceinline__ void cp_wait0() {
    asm volatile("cp.async.wait_group 0;" ::: "memory");
}
static __device__ __forceinline__ void prefetch_l2(const void* p) {
    asm volatile("prefetch.global.L2 [%0];" :: "l"(p));
}
// pack two fp32 into f16x2 reg: low half = x0 (even k), high half = x1
static __device__ __forceinline__ uint32_t pack_h2(float x0, float x1) {
    uint32_t r;
    asm("cvt.rn.f16x2.f32 %0, %1, %2;" : "=r"(r) : "f"(x1), "f"(x0));
    return r;
}
// split (x0,x1) into fp16 hi pair + fp16 lo (residual) pair
static __device__ __forceinline__ uint32_t split_h2(float x0, float x1,
                                                    uint32_t& lo) {
    uint32_t hi = pack_h2(x0, x1);
    half2 h = *reinterpret_cast<half2*>(&hi);
    float2 b = __half22float2(h);
    lo = pack_h2(x0 - b.x, x1 - b.y);
    return hi;
}
// D += A(16x16) * B(16x8), fp16 inputs, fp32 accum.
static __device__ __forceinline__ void mma16816(float& d0, float& d1, float& d2,
                                                float& d3, uint32_t a0,
                                                uint32_t a1, uint32_t a2,
                                                uint32_t a3, uint32_t b0,
                                                uint32_t b1) {
    asm("mma.sync.aligned.m16n8k16.row.col.f32.f16.f16.f32 "
        "{%0,%1,%2,%3}, {%4,%5,%6,%7}, {%8,%9}, {%0,%1,%2,%3};"
        : "+f"(d0), "+f"(d1), "+f"(d2), "+f"(d3)
        : "r"(a0), "r"(a1), "r"(a2), "r"(a3), "r"(b0), "r"(b1));
}
static __device__ __forceinline__ float fast_sig(float x) {
    return __fdividef(1.0f, 1.0f + __expf(-x));
}
static __device__ __forceinline__ float fast_tanh(float x) {
    float t = __expf(-2.0f * fabsf(x));
    float r = __fdividef(1.0f - t, 1.0f + t);
    return copysignf(r, x);
}

// Scratch (device globals: allocation-free per harness rules)
__device__ float g_GI[62914560];         // [81920][768] input gates (+biases)
__device__ uint32_t g_IPk_hi[10485760];  // [81920 rows][128 kpair] f16x2 items
__device__ uint32_t g_IPk_lo[10485760];
__device__ uint32_t g_WihPk_hi[98304];   // [128 kpair][768 j] f16x2 W_ih^T
__device__ uint32_t g_WhhPk_hi[98304];   // [128 kpair][768 j] f16x2 W_hh^T

// ---------------------------------------------------------------------------
__global__ void prep_weights(const float* __restrict__ W_ih,
                             const float* __restrict__ W_hh) {
    int idx = blockIdx.x * 256 + threadIdx.x;  // 98304 = 128 kpair x 768 j
    if (idx >= 98304) return;
    int kp = idx / 768;
    int j = idx - kp * 768;
    g_WihPk_hi[idx] = pack_h2(W_ih[(size_t)j * 512 + 2 * kp],
                              W_ih[(size_t)j * 512 + 2 * kp + 1]);
    g_WhhPk_hi[idx] = pack_h2(W_hh[(size_t)j * 256 + 2 * kp],
                              W_hh[(size_t)j * 256 + 2 * kp + 1]);
}

__global__ void prep_items(const float* __restrict__ A) {
    // 81920 rows x 128 kpairs = 10485760 pairs; 10240 blocks x 256 thr x 4
    int base = blockIdx.x * 256 + threadIdx.x;
#pragma unroll
    for (int it = 0; it < 4; it++) {
        int i = base + it * 2621440;
        float2 v = ((const float2*)A)[i];
        uint32_t lo, hi = split_h2(v.x, v.y, lo);
        g_IPk_hi[i] = hi;
        g_IPk_lo[i] = lo;
    }
}

// ---------------------------------------------------------------------------
// GI[r, j] = sum_k items[r,k] * W_ih[j,k] (+ bias), 2-term fp16 split
// ((a_hi + a_lo) @ fp16(W_ih)). Block tile 128x128, 8 warps (2m x 4n).
// K chunked by 32 (16 kpairs), cp.async double-buffered.
// Grid = (6 j-blocks, 640 r-blocks): j inner => A tiles reused from L2.
__global__ void __launch_bounds__(256, 2) gi_tc(const float* __restrict__ b_ih,
                                                const float* __restrict__ b_hh) {
    extern __shared__ uint32_t smu[];
    // A: (2p+h)*2560 : [128 m][20] (16 kpair + 4 pad)
    // B: 10240 + p*2176 : [16 kpair][136] (132+4 pad, stride 136%32==8)
    const uint32_t sbase = smem_u32(smu);
    const int tid = threadIdx.x;
    const int lane = tid & 31, w = tid >> 5;
    const int gid = lane >> 2, tidg = lane & 3;
    const int mbase = (w >> 2) * 64, nbase = (w & 3) * 32;
    const int r0 = blockIdx.y * 128, j0 = blockIdx.x * 128;

    float acc[4][4][4];
#pragma unroll
    for (int mt = 0; mt < 4; mt++)
#pragma unroll
        for (int nt = 0; nt < 4; nt++)
#pragma unroll
            for (int c = 0; c < 4; c++) acc[mt][nt][c] = 0.0f;

    auto issue = [&](int c) {
        int p = c & 1;
        uint32_t aA = sbase + (uint32_t)(2 * p * 2560) * 4;
        uint32_t aB = sbase + (uint32_t)(10240 + p * 2176) * 4;
#pragma unroll
        for (int it = 0; it < 4; it++) {
            int f = tid + it * 256;           // 1024 cp16: [h][128 m][4 k4]
            int h = f >> 9, rem = f & 511;
            int m = rem >> 2, k4 = rem & 3;
            const uint32_t* src = (h ? g_IPk_lo : g_IPk_hi) +
                                  (size_t)(r0 + m) * 128 + c * 16 + k4 * 4;
            cp16(aA + (uint32_t)(h * 2560 + m * 20 + k4 * 4) * 4, src);
        }
#pragma unroll
        for (int it = 0; it < 2; it++) {
            int f = tid + it * 256;           // 512 cp16: [16 kp][32 j4]
            int kp = f >> 5, j4 = f & 31;
            cp16(aB + (uint32_t)(kp * 136 + j4 * 4) * 4,
                 g_WihPk_hi + (size_t)(c * 16 + kp) * 768 + j0 + j4 * 4);
        }
        cp_commit();
    };

    issue(0);
    for (int c = 0; c < 8; c++) {
        if (c + 1 < 8) { issue(c + 1); cp_wait1(); } else { cp_wait0(); }
        __syncthreads();
        const uint32_t* Ah = smu + 2 * (c & 1) * 2560;
        const uint32_t* Al = Ah + 2560;
        const uint32_t* Bh = smu + 10240 + (c & 1) * 2176;
#pragma unroll
        for (int ks = 0; ks < 2; ks++) {
            const int kp0 = 8 * ks + tidg, kp1 = kp0 + 4;
            uint32_t bh[4][2];
#pragma unroll
            for (int nt = 0; nt < 4; nt++) {
                int j = nbase + 8 * nt + gid;
                bh[nt][0] = Bh[kp0 * 136 + j];
                bh[nt][1] = Bh[kp1 * 136 + j];
            }
#pragma unroll
            for (int mt = 0; mt < 4; mt++) {
                int row = mbase + 16 * mt + gid;
                uint32_t ah0 = Ah[row * 20 + kp0];
                uint32_t ah1 = Ah[(row + 8) * 20 + kp0];
                uint32_t ah2 = Ah[row * 20 + kp1];
                uint32_t ah3 = Ah[(row + 8) * 20 + kp1];
                uint32_t al0 = Al[row * 20 + kp0];
                uint32_t al1 = Al[(row + 8) * 20 + kp0];
                uint32_t al2 = Al[row * 20 + kp1];
                uint32_t al3 = Al[(row + 8) * 20 + kp1];
#pragma unroll
                for (int nt = 0; nt < 4; nt++) {
                    mma16816(acc[mt][nt][0], acc[mt][nt][1], acc[mt][nt][2],
                             acc[mt][nt][3], ah0, ah1, ah2, ah3,
                             bh[nt][0], bh[nt][1]);
                    mma16816(acc[mt][nt][0], acc[mt][nt][1], acc[mt][nt][2],
                             acc[mt][nt][3], al0, al1, al2, al3,
                             bh[nt][0], bh[nt][1]);
                }
            }
        }
        __syncthreads();  // buffer reuse guard before next issue
    }

    // epilogue: add bias, store float2s
    const bool addh = (j0 + nbase) < 512;
    float2 bias[4];
#pragma unroll
    for (int nt = 0; nt < 4; nt++) {
        int j = j0 + nbase + 8 * nt + 2 * tidg;
        float2 v = *(const float2*)(b_ih + j);
        if (addh) {
            float2 h2 = *(const float2*)(b_hh + j);
            v.x += h2.x; v.y += h2.y;
        }
        bias[nt] = v;
    }
#pragma unroll
    for (int mt = 0; mt < 4; mt++)
#pragma unroll
        for (int rh = 0; rh < 2; rh++) {
            int row = mbase + 16 * mt + 8 * rh + gid;
            float* dst = g_GI + (size_t)(r0 + row) * 768 + j0 + nbase;
#pragma unroll
            for (int nt = 0; nt < 4; nt++) {
                float2 o;
                o.x = acc[mt][nt][2 * rh] + bias[nt].x;
                o.y = acc[mt][nt][2 * rh + 1] + bias[nt].y;
                *(float2*)(dst + 8 * nt + 2 * tidg) = o;
            }
        }
}

// ---------------------------------------------------------------------------
// RNN (= R8, best measured 297us): one CTA per batch (128 CTAs, 512 thr).
// h in SMEM as f16x2 hi/lo; warp w owns d in [16w, 16w+16) for all 3 gates
// => epilogue fully in-warp. 2-term split: (h_hi + h_lo) @ fp16(W_hh).
// Weights staged per 16-kpair chunk (8 chunks/step) via cp.async,
// double-buffered; B fragments shared across the two h passes.
__global__ void __launch_bounds__(512) rnn_tc(const float* __restrict__ user_embs,
                                              const float* __restrict__ b_hh,
                                              const float* __restrict__ w_out,
                                              const float* __restrict__ b_out,
                                              const int* __restrict__ length,
                                              float* __restrict__ out) {
    extern __shared__ uint32_t smu[];
    uint32_t* hsm_hi = smu;            // [64][132] (128 kpair + 4 pad)
    uint32_t* hsm_lo = smu + 8448;
    // weight bufs @16896 + p*12416 : [16 kp][776]
    float* ysm = (float*)(smu + 41728);  // [64]
    const uint32_t sbase = smem_u32(smu);

    const int b = blockIdx.x;
    const int tid = threadIdx.x;
    const int lane = tid & 31, w = tid >> 5;
    const int gid = lane >> 2, tidg = lane & 3;
    const int dbase = w * 16;

    // h0 = user_embs[b, clip(len-1,0)] broadcast to 64 rows, split to f16 hi/lo
    int hidx = length[b] - 1;
    if (hidx < 0) hidx = 0;
    const float* u0 = user_embs + ((size_t)b * 64 + hidx) * 256;
    for (int i = tid; i < 64 * 128; i += 512) {
        int row = i >> 7, kp = i & 127;
        float2 v = *(const float2*)(u0 + 2 * kp);
        uint32_t lo, hi = split_h2(v.x, v.y, lo);
        hsm_hi[row * 132 + kp] = hi;
        hsm_lo[row * 132 + kp] = lo;
    }
    const float bout = b_out[0];
    if (tid < 64) ysm[tid] = bout;

    float2 bhn[2], wo[2];
#pragma unroll
    for (int nt = 0; nt < 2; nt++) {
        int d = dbase + 8 * nt + 2 * tidg;
        bhn[nt] = *(const float2*)(b_hh + 512 + d);
        wo[nt] = *(const float2*)(w_out + d);
    }

    auto issue = [&](int c) {
        int p = c & 1;
#pragma unroll
        for (int it = 0; it < 6; it++) {
            int f = tid + it * 512;        // 3072 cp16: [16 kk][192 j4]
            int kk = f / 192, j4 = f - kk * 192;
            cp16(sbase + (uint32_t)(16896 + p * 12416 + kk * 776 + j4 * 4) * 4,
                 g_WhhPk_hi + (size_t)(c * 16 + kk) * 768 + j4 * 4);
        }
        cp_commit();
    };

    float acc[4][3][2][4];

    for (int k = 0; k < 10; k++) {
        // prefetch this step's GI slab (64 rows x 768 floats) into L2
        {
            const float* gib = g_GI + ((size_t)(b * 64) * 10 + k) * 768;
            for (int i = tid; i < 1536; i += 512) {
                int r = i / 24, l = i - r * 24;
                prefetch_l2((const char*)(gib + (size_t)r * 7680) + l * 128);
            }
        }
#pragma unroll
        for (int mt = 0; mt < 4; mt++)
#pragma unroll
            for (int g = 0; g < 3; g++)
#pragma unroll
                for (int nt = 0; nt < 2; nt++)
#pragma unroll
                    for (int c = 0; c < 4; c++) acc[mt][g][nt][c] = 0.0f;

        issue(0);
        for (int c = 0; c < 8; c++) {
            if (c + 1 < 8) { issue(c + 1); cp_wait1(); } else { cp_wait0(); }
            __syncthreads();
            const uint32_t* wb = smu + 16896 + (c & 1) * 12416;
#pragma unroll
            for (int ks = 0; ks < 2; ks++) {
                // B fragments (w_hi), shared by both h passes
                uint32_t bfr[6][2];
#pragma unroll
                for (int g = 0; g < 3; g++)
#pragma unroll
                    for (int nt = 0; nt < 2; nt++) {
                        int n = g * 256 + dbase + 8 * nt + gid;
                        bfr[g * 2 + nt][0] = wb[(8 * ks + tidg) * 776 + n];
                        bfr[g * 2 + nt][1] = wb[(8 * ks + tidg + 4) * 776 + n];
                    }
                const int kpc = 16 * c + 8 * ks;
#pragma unroll
                for (int pass = 0; pass < 2; pass++) {
                    const uint32_t* hb = pass ? hsm_lo : hsm_hi;
#pragma unroll
                    for (int mt = 0; mt < 4; mt++) {
                        int row = 16 * mt + gid;
                        uint32_t a0 = hb[row * 132 + kpc + tidg];
                        uint32_t a1 = hb[(row + 8) * 132 + kpc + tidg];
                        uint32_t a2 = hb[row * 132 + kpc + 4 + tidg];
                        uint32_t a3 = hb[(row + 8) * 132 + kpc + 4 + tidg];
#pragma unroll
                        for (int g = 0; g < 3; g++)
#pragma unroll
                            for (int nt = 0; nt < 2; nt++)
                                mma16816(acc[mt][g][nt][0], acc[mt][g][nt][1],
                                         acc[mt][g][nt][2], acc[mt][g][nt][3],
                                         a0, a1, a2, a3,
                                         bfr[g * 2 + nt][0], bfr[g * 2 + nt][1]);
                    }
                }
            }
            __syncthreads();  // buffer reuse guard; last iter: pre-epilogue guard
        }

        // fused GRU epilogue (each (row,d) cell owned by exactly one thread)
#pragma unroll
        for (int mt = 0; mt < 4; mt++)
#pragma unroll
            for (int rh = 0; rh < 2; rh++) {
                int row = 16 * mt + 8 * rh + gid;
                const float* gi = g_GI + ((size_t)(b * 64 + row) * 10 + k) * 768;
                float yp = 0.0f;
#pragma unroll
                for (int nt = 0; nt < 2; nt++) {
                    int d = dbase + 8 * nt + 2 * tidg;
                    int kp = d >> 1;
                    float2 gr = *(const float2*)(gi + d);
                    float2 gz = *(const float2*)(gi + 256 + d);
                    float2 gn = *(const float2*)(gi + 512 + d);
                    uint32_t hh = hsm_hi[row * 132 + kp];
                    uint32_t hl = hsm_lo[row * 132 + kp];
                    float2 hhf = __half22float2(*reinterpret_cast<half2*>(&hh));
                    float2 hlf = __half22float2(*reinterpret_cast<half2*>(&hl));
                    float hox = hhf.x + hlf.x, hoy = hhf.y + hlf.y;
                    int c0 = rh * 2;
                    float r0v = fast_sig(gr.x + acc[mt][0][nt][c0]);
                    float r1v = fast_sig(gr.y + acc[mt][0][nt][c0 + 1]);
                    float z0v = fast_sig(gz.x + acc[mt][1][nt][c0]);
                    float z1v = fast_sig(gz.y + acc[mt][1][nt][c0 + 1]);
                    float hn0 = acc[mt][2][nt][c0] + bhn[nt].x;
                    float hn1 = acc[mt][2][nt][c0 + 1] + bhn[nt].y;
                    float n0 = fast_tanh(gn.x + r0v * hn0);
                    float n1 = fast_tanh(gn.y + r1v * hn1);
                    float h0n = (1.0f - z0v) * n0 + z0v * hox;
                    float h1n = (1.0f - z1v) * n1 + z1v * hoy;
                    uint32_t nlo, nhi = split_h2(h0n, h1n, nlo);
                    hsm_hi[row * 132 + kp] = nhi;
                    hsm_lo[row * 132 + kp] = nlo;
                    yp += h0n * wo[nt].x + h1n * wo[nt].y;
                }
                yp += __shfl_xor_sync(0xffffffffu, yp, 1);
                yp += __shfl_xor_sync(0xffffffffu, yp, 2);
                if (tidg == 0) atomicAdd(&ysm[row], yp);
            }
        __syncthreads();
        if (tid < 64) {
            out[((size_t)(b * 64) + tid) * 10 + k] = ysm[tid];
            ysm[tid] = bout;
        }
        __syncthreads();  // order out-write/ysm-reset + h writes before next step
    }
}

// ---------------------------------------------------------------------------
extern "C" void kernel_launch(void* const* d_in, const int* in_sizes, int n_in,
                              void* d_out, int out_size) {
    (void)in_sizes; (void)n_in; (void)out_size;
    const float* item_embs = (const float*)d_in[0];  // [128,64,10,256]
    const float* user_embs = (const float*)d_in[1];  // [128,64,256]
    const float* W_ih      = (const float*)d_in[2];  // [768,512]
    const float* W_hh      = (const float*)d_in[3];  // [768,256]
    const float* b_ih      = (const float*)d_in[4];  // [768]
    const float* b_hh      = (const float*)d_in[5];  // [768]
    const float* w_out     = (const float*)d_in[6];  // [256]
    const float* b_out     = (const float*)d_in[7];  // scalar
    const int*   length    = (const int*)d_in[8];    // [128]
    float* out = (float*)d_out;                      // [128,64,10]

    prep_weights<<<384, 256>>>(W_ih, W_hh);
    prep_items<<<10240, 256>>>(item_embs);

    const int gi_smem = 14592 * 4;  // 58368 B
    cudaFuncSetAttribute(gi_tc, cudaFuncAttributeMaxDynamicSharedMemorySize,
                         gi_smem);
    dim3 gg(6, 640);  // j-blocks inner => A-tile L2 reuse across 6 j-blocks
    gi_tc<<<gg, 256, gi_smem>>>(b_ih, b_hh);

    const int rnn_smem = 41792 * 4;  // 167168 B
    cudaFuncSetAttribute(rnn_tc, cudaFuncAttributeMaxDynamicSharedMemorySize,
                         rnn_smem);
    rnn_tc<<<128, 512, rnn_smem>>>(user_embs, b_hh, w_out, b_out, length, out);
}

// round 16
// speedup vs baseline: 1.6704x; 1.1309x over previous
#include <cuda_runtime.h>
#include <cuda_fp16.h>
#include <cstdint>
#include <math.h>

// SlatewiseGRU: B=128, S=64, K=10, D=256.
// Input second half is zeros => threshold mask dead, GI GEMM hoisted.
// R15: gi -> 1-term (fp16 items @ fp16 W_ih): halves gi mma + staging.
// rnn: R14 shape + triple-buffered weight staging (1 barrier/chunk) and
// next-step stage issue hoisted before the epilogue (overlap).

// ---------------------------------------------------------------------------
static __device__ __forceinline__ uint32_t smem_u32(const void* p) {
    uint32_t a;
    asm("{ .reg .u64 t; cvta.to.shared.u64 t, %1; cvt.u32.u64 %0, t; }"
        : "=r"(a) : "l"(p));
    return a;
}
static __device__ __forceinline__ void cp16(uint32_t dst, const void* src) {
    asm volatile("cp.async.cg.shared.global [%0], [%1], 16;"
                 :: "r"(dst), "l"(src));
}
static __device__ __forceinline__ void cp_commit() {
    asm volatile("cp.async.commit_group;" ::: "memory");
}
static __device__ __forceinline__ void cp_wait1() {
    asm volatile("cp.async.wait_group 1;" ::: "memory");
}
static __device__ __forceinline__ void cp_wait0() {
    asm volatile("cp.async.wait_group 0;" ::: "memory");
}
static __device__ __forceinline__ void prefetch_l2(const void* p) {
    asm volatile("prefetch.global.L2 [%0];" :: "l"(p));
}
// pack two fp32 into f16x2 reg: low half = x0 (even k), high half = x1
static __device__ __forceinline__ uint32_t pack_h2(float x0, float x1) {
    uint32_t r;
    asm("cvt.rn.f16x2.f32 %0, %1, %2;" : "=r"(r) : "f"(x1), "f"(x0));
    return r;
}
// split (x0,x1) into fp16 hi pair + fp16 lo (residual) pair
static __device__ __forceinline__ uint32_t split_h2(float x0, float x1,
                                                    uint32_t& lo) {
    uint32_t hi = pack_h2(x0, x1);
    half2 h = *reinterpret_cast<half2*>(&hi);
    float2 b = __half22float2(h);
    lo = pack_h2(x0 - b.x, x1 - b.y);
    return hi;
}
// D += A(16x16) * B(16x8), fp16 inputs, fp32 accum.
static __device__ __forceinline__ void mma16816(float& d0, float& d1, float& d2,
                                                float& d3, uint32_t a0,
                                                uint32_t a1, uint32_t a2,
                                                uint32_t a3, uint32_t b0,
                                                uint32_t b1) {
    asm("mma.sync.aligned.m16n8k16.row.col.f32.f16.f16.f32 "
        "{%0,%1,%2,%3}, {%4,%5,%6,%7}, {%8,%9}, {%0,%1,%2,%3};"
        : "+f"(d0), "+f"(d1), "+f"(d2), "+f"(d3)
        : "r"(a0), "r"(a1), "r"(a2), "r"(a3), "r"(b0), "r"(b1));
}
static __device__ __forceinline__ float fast_sig(float x) {
    return __fdividef(1.0f, 1.0f + __expf(-x));
}
static __device__ __forceinline__ float fast_tanh(float x) {
    float t = __expf(-2.0f * fabsf(x));
    float r = __fdividef(1.0f - t, 1.0f + t);
    return copysignf(r, x);
}

// Scratch (device globals: allocation-free per harness rules)
__device__ float g_GI[62914560];         // [81920][768] input gates (+biases)
__device__ uint32_t g_IPk_hi[10485760];  // [81920 rows][128 kpair] f16x2 items
__device__ uint32_t g_WihPk_hi[98304];   // [128 kpair][768 j] f16x2 W_ih^T
__device__ uint32_t g_WhhPk_hi[98304];   // [128 kpair][768 j] f16x2 W_hh^T

// ---------------------------------------------------------------------------
__global__ void prep_weights(const float* __restrict__ W_ih,
                             const float* __restrict__ W_hh) {
    int idx = blockIdx.x * 256 + threadIdx.x;  // 98304 = 128 kpair x 768 j
    if (idx >= 98304) return;
    int kp = idx / 768;
    int j = idx - kp * 768;
    g_WihPk_hi[idx] = pack_h2(W_ih[(size_t)j * 512 + 2 * kp],
                              W_ih[(size_t)j * 512 + 2 * kp + 1]);
    g_WhhPk_hi[idx] = pack_h2(W_hh[(size_t)j * 256 + 2 * kp],
                              W_hh[(size_t)j * 256 + 2 * kp + 1]);
}

__global__ void prep_items(const float* __restrict__ A) {
    // 81920 rows x 128 kpairs = 10485760 pairs; 10240 blocks x 256 thr x 4
    int base = blockIdx.x * 256 + threadIdx.x;
#pragma unroll
    for (int it = 0; it < 4; it++) {
        int i = base + it * 2621440;
        float2 v = ((const float2*)A)[i];
        g_IPk_hi[i] = pack_h2(v.x, v.y);
    }
}

// ---------------------------------------------------------------------------
// GI[r, j] = sum_k fp16(items[r,k]) * fp16(W_ih[j,k]) (+ bias), 1-term.
// Block tile 128x128, 8 warps (2m x 4n). K chunked by 32 (16 kpairs),
// cp.async double-buffered.
// Grid = (6 j-blocks, 640 r-blocks): j inner => A tiles reused from L2.
__global__ void __launch_bounds__(256, 2) gi_tc(const float* __restrict__ b_ih,
                                                const float* __restrict__ b_hh) {
    extern __shared__ uint32_t smu[];
    // A: p*2560 : [128 m][20] (16 kpair + 4 pad)
    // B: 5120 + p*2176 : [16 kpair][136] (132+4 pad, stride 136%32==8)
    const uint32_t sbase = smem_u32(smu);
    const int tid = threadIdx.x;
    const int lane = tid & 31, w = tid >> 5;
    const int gid = lane >> 2, tidg = lane & 3;
    const int mbase = (w >> 2) * 64, nbase = (w & 3) * 32;
    const int r0 = blockIdx.y * 128, j0 = blockIdx.x * 128;

    float acc[4][4][4];
#pragma unroll
    for (int mt = 0; mt < 4; mt++)
#pragma unroll
        for (int nt = 0; nt < 4; nt++)
#pragma unroll
            for (int c = 0; c < 4; c++) acc[mt][nt][c] = 0.0f;

    auto issue = [&](int c) {
        int p = c & 1;
        uint32_t aA = sbase + (uint32_t)(p * 2560) * 4;
        uint32_t aB = sbase + (uint32_t)(5120 + p * 2176) * 4;
#pragma unroll
        for (int it = 0; it < 2; it++) {
            int f = tid + it * 256;           // 512 cp16: [128 m][4 k4]
            int m = f >> 2, k4 = f & 3;
            cp16(aA + (uint32_t)(m * 20 + k4 * 4) * 4,
                 g_IPk_hi + (size_t)(r0 + m) * 128 + c * 16 + k4 * 4);
        }
#pragma unroll
        for (int it = 0; it < 2; it++) {
            int f = tid + it * 256;           // 512 cp16: [16 kp][32 j4]
            int kp = f >> 5, j4 = f & 31;
            cp16(aB + (uint32_t)(kp * 136 + j4 * 4) * 4,
                 g_WihPk_hi + (size_t)(c * 16 + kp) * 768 + j0 + j4 * 4);
        }
        cp_commit();
    };

    issue(0);
    for (int c = 0; c < 8; c++) {
        if (c + 1 < 8) { issue(c + 1); cp_wait1(); } else { cp_wait0(); }
        __syncthreads();
        const uint32_t* Ah = smu + (c & 1) * 2560;
        const uint32_t* Bh = smu + 5120 + (c & 1) * 2176;
#pragma unroll
        for (int ks = 0; ks < 2; ks++) {
            const int kp0 = 8 * ks + tidg, kp1 = kp0 + 4;
            uint32_t bh[4][2];
#pragma unroll
            for (int nt = 0; nt < 4; nt++) {
                int j = nbase + 8 * nt + gid;
                bh[nt][0] = Bh[kp0 * 136 + j];
                bh[nt][1] = Bh[kp1 * 136 + j];
            }
#pragma unroll
            for (int mt = 0; mt < 4; mt++) {
                int row = mbase + 16 * mt + gid;
                uint32_t ah0 = Ah[row * 20 + kp0];
                uint32_t ah1 = Ah[(row + 8) * 20 + kp0];
                uint32_t ah2 = Ah[row * 20 + kp1];
                uint32_t ah3 = Ah[(row + 8) * 20 + kp1];
#pragma unroll
                for (int nt = 0; nt < 4; nt++)
                    mma16816(acc[mt][nt][0], acc[mt][nt][1], acc[mt][nt][2],
                             acc[mt][nt][3], ah0, ah1, ah2, ah3,
                             bh[nt][0], bh[nt][1]);
            }
        }
        __syncthreads();  // buffer reuse guard before next issue
    }

    // epilogue: add bias, store float2s
    const bool addh = (j0 + nbase) < 512;
    float2 bias[4];
#pragma unroll
    for (int nt = 0; nt < 4; nt++) {
        int j = j0 + nbase + 8 * nt + 2 * tidg;
        float2 v = *(const float2*)(b_ih + j);
        if (addh) {
            float2 h2 = *(const float2*)(b_hh + j);
            v.x += h2.x; v.y += h2.y;
        }
        bias[nt] = v;
    }
#pragma unroll
    for (int mt = 0; mt < 4; mt++)
#pragma unroll
        for (int rh = 0; rh < 2; rh++) {
            int row = mbase + 16 * mt + 8 * rh + gid;
            float* dst = g_GI + (size_t)(r0 + row) * 768 + j0 + nbase;
#pragma unroll
            for (int nt = 0; nt < 4; nt++) {
                float2 o;
                o.x = acc[mt][nt][2 * rh] + bias[nt].x;
                o.y = acc[mt][nt][2 * rh + 1] + bias[nt].y;
                *(float2*)(dst + 8 * nt + 2 * tidg) = o;
            }
        }
}

// ---------------------------------------------------------------------------
// RNN (R8/R14 shape): one CTA per batch (128 CTAs, 512 thr).
// h in SMEM as f16x2 hi/lo; warp w owns d in [16w, 16w+16) for all 3 gates
// => epilogue fully in-warp. 2-term split: (h_hi + h_lo) @ fp16(W_hh).
// R15: weights TRIPLE-buffered (1 barrier per 16-kpair chunk); next step's
// chunk-0/1 staging issued before the epilogue (weights independent of h).
__global__ void __launch_bounds__(512) rnn_tc(const float* __restrict__ user_embs,
                                              const float* __restrict__ b_hh,
                                              const float* __restrict__ w_out,
                                              const float* __restrict__ b_out,
                                              const int* __restrict__ length,
                                              float* __restrict__ out) {
    extern __shared__ uint32_t smu[];
    uint32_t* hsm_hi = smu;            // [64][132] (128 kpair + 4 pad)
    uint32_t* hsm_lo = smu + 8448;
    // weight bufs @16896 + (c%3)*12416 : [16 kp][776]
    float* ysm = (float*)(smu + 54144);  // [64]
    const uint32_t sbase = smem_u32(smu);

    const int b = blockIdx.x;
    const int tid = threadIdx.x;
    const int lane = tid & 31, w = tid >> 5;
    const int gid = lane >> 2, tidg = lane & 3;
    const int dbase = w * 16;

    // h0 = user_embs[b, clip(len-1,0)] broadcast to 64 rows, split to f16 hi/lo
    int hidx = length[b] - 1;
    if (hidx < 0) hidx = 0;
    const float* u0 = user_embs + ((size_t)b * 64 + hidx) * 256;
    for (int i = tid; i < 64 * 128; i += 512) {
        int row = i >> 7, kp = i & 127;
        float2 v = *(const float2*)(u0 + 2 * kp);
        uint32_t lo, hi = split_h2(v.x, v.y, lo);
        hsm_hi[row * 132 + kp] = hi;
        hsm_lo[row * 132 + kp] = lo;
    }
    const float bout = b_out[0];
    if (tid < 64) ysm[tid] = bout;

    float2 bhn[2], wo[2];
#pragma unroll
    for (int nt = 0; nt < 2; nt++) {
        int d = dbase + 8 * nt + 2 * tidg;
        bhn[nt] = *(const float2*)(b_hh + 512 + d);
        wo[nt] = *(const float2*)(w_out + d);
    }

    auto issue = [&](int c) {
        int bf = c - (c / 3) * 3;  // c % 3
#pragma unroll
        for (int it = 0; it < 6; it++) {
            int f = tid + it * 512;        // 3072 cp16: [16 kk][192 j4]
            int kk = f / 192, j4 = f - kk * 192;
            cp16(sbase + (uint32_t)(16896 + bf * 12416 + kk * 776 + j4 * 4) * 4,
                 g_WhhPk_hi + (size_t)(c * 16 + kk) * 768 + j4 * 4);
        }
        cp_commit();
    };

    float acc[4][3][2][4];

    // Stage step-0 chunks 0,1 up front (triple-buffered).
    issue(0);
    issue(1);

    for (int k = 0; k < 10; k++) {
        // prefetch this step's GI slab (64 rows x 768 floats) into L2
        {
            const float* gib = g_GI + ((size_t)(b * 64) * 10 + k) * 768;
            for (int i = tid; i < 1536; i += 512) {
                int r = i / 24, l = i - r * 24;
                prefetch_l2((const char*)(gib + (size_t)r * 7680) + l * 128);
            }
        }
#pragma unroll
        for (int mt = 0; mt < 4; mt++)
#pragma unroll
            for (int g = 0; g < 3; g++)
#pragma unroll
                for (int nt = 0; nt < 2; nt++)
#pragma unroll
                    for (int c = 0; c < 4; c++) acc[mt][g][nt][c] = 0.0f;

        for (int c = 0; c < 8; c++) {
            if (c < 7) cp_wait1(); else cp_wait0();
            __syncthreads();   // single barrier per chunk (triple buffer);
                               // chunk c+2's buffer ((c+2)%3==(c-1)%3) was
                               // fully consumed by chunk c-1 before this bar.
            if (c < 6) issue(c + 2);
            const uint32_t* wb = smu + 16896 + (c - (c / 3) * 3) * 12416;
#pragma unroll
            for (int ks = 0; ks < 2; ks++) {
                // B fragments (w_hi), shared by both h passes
                uint32_t bfr[6][2];
#pragma unroll
                for (int g = 0; g < 3; g++)
#pragma unroll
                    for (int nt = 0; nt < 2; nt++) {
                        int n = g * 256 + dbase + 8 * nt + gid;
                        bfr[g * 2 + nt][0] = wb[(8 * ks + tidg) * 776 + n];
                        bfr[g * 2 + nt][1] = wb[(8 * ks + tidg + 4) * 776 + n];
                    }
                const int kpc = 16 * c + 8 * ks;
#pragma unroll
                for (int pass = 0; pass < 2; pass++) {
                    const uint32_t* hb = pass ? hsm_lo : hsm_hi;
#pragma unroll
                    for (int mt = 0; mt < 4; mt++) {
                        int row = 16 * mt + gid;
                        uint32_t a0 = hb[row * 132 + kpc + tidg];
                        uint32_t a1 = hb[(row + 8) * 132 + kpc + tidg];
                        uint32_t a2 = hb[row * 132 + kpc + 4 + tidg];
                        uint32_t a3 = hb[(row + 8) * 132 + kpc + 4 + tidg];
#pragma unroll
                        for (int g = 0; g < 3; g++)
#pragma unroll
                            for (int nt = 0; nt < 2; nt++)
                                mma16816(acc[mt][g][nt][0], acc[mt][g][nt][1],
                                         acc[mt][g][nt][2], acc[mt][g][nt][3],
                                         a0, a1, a2, a3,
                                         bfr[g * 2 + nt][0], bfr[g * 2 + nt][1]);
                    }
                }
            }
        }
        __syncthreads();  // all h reads + last chunk's buffer reads done

        // Hoist next step's chunk-0/1 staging: buffers 0 (chunk 6) and 1
        // (chunk 7) are free after the barrier above; weights don't depend
        // on h/ysm, so this overlaps the epilogue.
        if (k < 9) { issue(0); issue(1); }

        // fused GRU epilogue (each (row,d) cell owned by exactly one thread)
#pragma unroll
        for (int mt = 0; mt < 4; mt++)
#pragma unroll
            for (int rh = 0; rh < 2; rh++) {
                int row = 16 * mt + 8 * rh + gid;
                const float* gi = g_GI + ((size_t)(b * 64 + row) * 10 + k) * 768;
                float yp = 0.0f;
#pragma unroll
                for (int nt = 0; nt < 2; nt++) {
                    int d = dbase + 8 * nt + 2 * tidg;
                    int kp = d >> 1;
                    float2 gr = *(const float2*)(gi + d);
                    float2 gz = *(const float2*)(gi + 256 + d);
                    float2 gn = *(const float2*)(gi + 512 + d);
                    uint32_t hh = hsm_hi[row * 132 + kp];
                    uint32_t hl = hsm_lo[row * 132 + kp];
                    float2 hhf = __half22float2(*reinterpret_cast<half2*>(&hh));
                    float2 hlf = __half22float2(*reinterpret_cast<half2*>(&hl));
                    float hox = hhf.x + hlf.x, hoy = hhf.y + hlf.y;
                    int c0 = rh * 2;
                    float r0v = fast_sig(gr.x + acc[mt][0][nt][c0]);
                    float r1v = fast_sig(gr.y + acc[mt][0][nt][c0 + 1]);
                    float z0v = fast_sig(gz.x + acc[mt][1][nt][c0]);
                    float z1v = fast_sig(gz.y + acc[mt][1][nt][c0 + 1]);
                    float hn0 = acc[mt][2][nt][c0] + bhn[nt].x;
                    float hn1 = acc[mt][2][nt][c0 + 1] + bhn[nt].y;
                    float n0 = fast_tanh(gn.x + r0v * hn0);
                    float n1 = fast_tanh(gn.y + r1v * hn1);
                    float h0n = (1.0f - z0v) * n0 + z0v * hox;
                    float h1n = (1.0f - z1v) * n1 + z1v * hoy;
                    uint32_t nlo, nhi = split_h2(h0n, h1n, nlo);
                    hsm_hi[row * 132 + kp] = nhi;
                    hsm_lo[row * 132 + kp] = nlo;
                    yp += h0n * wo[nt].x + h1n * wo[nt].y;
                }
                yp += __shfl_xor_sync(0xffffffffu, yp, 1);
                yp += __shfl_xor_sync(0xffffffffu, yp, 2);
                if (tidg == 0) atomicAdd(&ysm[row], yp);
            }
        __syncthreads();
        if (tid < 64) {
            out[((size_t)(b * 64) + tid) * 10 + k] = ysm[tid];
            ysm[tid] = bout;
        }
        // next step's chunk-0 barrier orders h/ysm writes vs reads
    }
}

// ---------------------------------------------------------------------------
extern "C" void kernel_launch(void* const* d_in, const int* in_sizes, int n_in,
                              void* d_out, int out_size) {
    (void)in_sizes; (void)n_in; (void)out_size;
    const float* item_embs = (const float*)d_in[0];  // [128,64,10,256]
    const float* user_embs = (const float*)d_in[1];  // [128,64,256]
    const float* W_ih      = (const float*)d_in[2];  // [768,512]
    const float* W_hh      = (const float*)d_in[3];  // [768,256]
    const float* b_ih      = (const float*)d_in[4];  // [768]
    const float* b_hh      = (const float*)d_in[5];  // [768]
    const float* w_out     = (const float*)d_in[6];  // [256]
    const float* b_out     = (const float*)d_in[7];  // scalar
    const int*   length    = (const int*)d_in[8];    // [128]
    float* out = (float*)d_out;                      // [128,64,10]

    prep_weights<<<384, 256>>>(W_ih, W_hh);
    prep_items<<<10240, 256>>>(item_embs);

    const int gi_smem = 9472 * 4;  // 37888 B
    cudaFuncSetAttribute(gi_tc, cudaFuncAttributeMaxDynamicSharedMemorySize,
                         gi_smem);
    dim3 gg(6, 640);  // j-blocks inner => A-tile L2 reuse across 6 j-blocks
    gi_tc<<<gg, 256, gi_smem>>>(b_ih, b_hh);

    const int rnn_smem = 54208 * 4;  // 216832 B
    cudaFuncSetAttribute(rnn_tc, cudaFuncAttributeMaxDynamicSharedMemorySize,
                         rnn_smem);
    rnn_tc<<<128, 512, rnn_smem>>>(user_embs, b_hh, w_out, b_out, length, out);
}

// round 17
// speedup vs baseline: 1.7440x; 1.0441x over previous
#include <cuda_runtime.h>
#include <cuda_fp16.h>
#include <cstdint>
#include <math.h>

// SlatewiseGRU: B=128, S=64, K=10, D=256.
// Input second half is zeros => threshold mask dead, GI GEMM hoisted.
// R16: recombine best-measured components.
//  rnn = R14 exactly (double-buffered 16-kpair chunks, 2 barriers/chunk;
//        292us measured — beats triple-buffer variants in R12/R15 twice).
//  gi  = R15 exactly (1-term fp16 items @ fp16 W_ih; ~160us incl. preps).

// ---------------------------------------------------------------------------
static __device__ __forceinline__ uint32_t smem_u32(const void* p) {
    uint32_t a;
    asm("{ .reg .u64 t; cvta.to.shared.u64 t, %1; cvt.u32.u64 %0, t; }"
        : "=r"(a) : "l"(p));
    return a;
}
static __device__ __forceinline__ void cp16(uint32_t dst, const void* src) {
    asm volatile("cp.async.cg.shared.global [%0], [%1], 16;"
                 :: "r"(dst), "l"(src));
}
static __device__ __forceinline__ void cp_commit() {
    asm volatile("cp.async.commit_group;" ::: "memory");
}
static __device__ __forceinline__ void cp_wait1() {
    asm volatile("cp.async.wait_group 1;" ::: "memory");
}
static __device__ __forceinline__ void cp_wait0() {
    asm volatile("cp.async.wait_group 0;" ::: "memory");
}
static __device__ __forceinline__ void prefetch_l2(const void* p) {
    asm volatile("prefetch.global.L2 [%0];" :: "l"(p));
}
// pack two fp32 into f16x2 reg: low half = x0 (even k), high half = x1
static __device__ __forceinline__ uint32_t pack_h2(float x0, float x1) {
    uint32_t r;
    asm("cvt.rn.f16x2.f32 %0, %1, %2;" : "=r"(r) : "f"(x1), "f"(x0));
    return r;
}
// split (x0,x1) into fp16 hi pair + fp16 lo (residual) pair
static __device__ __forceinline__ uint32_t split_h2(float x0, float x1,
                                                    uint32_t& lo) {
    uint32_t hi = pack_h2(x0, x1);
    half2 h = *reinterpret_cast<half2*>(&hi);
    float2 b = __half22float2(h);
    lo = pack_h2(x0 - b.x, x1 - b.y);
    return hi;
}
// D += A(16x16) * B(16x8), fp16 inputs, fp32 accum.
static __device__ __forceinline__ void mma16816(float& d0, float& d1, float& d2,
                                                float& d3, uint32_t a0,
                                                uint32_t a1, uint32_t a2,
                                                uint32_t a3, uint32_t b0,
                                                uint32_t b1) {
    asm("mma.sync.aligned.m16n8k16.row.col.f32.f16.f16.f32 "
        "{%0,%1,%2,%3}, {%4,%5,%6,%7}, {%8,%9}, {%0,%1,%2,%3};"
        : "+f"(d0), "+f"(d1), "+f"(d2), "+f"(d3)
        : "r"(a0), "r"(a1), "r"(a2), "r"(a3), "r"(b0), "r"(b1));
}
static __device__ __forceinline__ float fast_sig(float x) {
    return __fdividef(1.0f, 1.0f + __expf(-x));
}
static __device__ __forceinline__ float fast_tanh(float x) {
    float t = __expf(-2.0f * fabsf(x));
    float r = __fdividef(1.0f - t, 1.0f + t);
    return copysignf(r, x);
}

// Scratch (device globals: allocation-free per harness rules)
__device__ float g_GI[62914560];         // [81920][768] input gates (+biases)
__device__ uint32_t g_IPk_hi[10485760];  // [81920 rows][128 kpair] f16x2 items
__device__ uint32_t g_WihPk_hi[98304];   // [128 kpair][768 j] f16x2 W_ih^T
__device__ uint32_t g_WhhPk_hi[98304];   // [128 kpair][768 j] f16x2 W_hh^T

// ---------------------------------------------------------------------------
__global__ void prep_weights(const float* __restrict__ W_ih,
                             const float* __restrict__ W_hh) {
    int idx = blockIdx.x * 256 + threadIdx.x;  // 98304 = 128 kpair x 768 j
    if (idx >= 98304) return;
    int kp = idx / 768;
    int j = idx - kp * 768;
    g_WihPk_hi[idx] = pack_h2(W_ih[(size_t)j * 512 + 2 * kp],
                              W_ih[(size_t)j * 512 + 2 * kp + 1]);
    g_WhhPk_hi[idx] = pack_h2(W_hh[(size_t)j * 256 + 2 * kp],
                              W_hh[(size_t)j * 256 + 2 * kp + 1]);
}

__global__ void prep_items(const float* __restrict__ A) {
    // 81920 rows x 128 kpairs = 10485760 pairs; 10240 blocks x 256 thr x 4
    int base = blockIdx.x * 256 + threadIdx.x;
#pragma unroll
    for (int it = 0; it < 4; it++) {
        int i = base + it * 2621440;
        float2 v = ((const float2*)A)[i];
        g_IPk_hi[i] = pack_h2(v.x, v.y);
    }
}

// ---------------------------------------------------------------------------
// GI[r, j] = sum_k fp16(items[r,k]) * fp16(W_ih[j,k]) (+ bias), 1-term.
// Block tile 128x128, 8 warps (2m x 4n). K chunked by 32 (16 kpairs),
// cp.async double-buffered.
// Grid = (6 j-blocks, 640 r-blocks): j inner => A tiles reused from L2.
__global__ void __launch_bounds__(256, 2) gi_tc(const float* __restrict__ b_ih,
                                                const float* __restrict__ b_hh) {
    extern __shared__ uint32_t smu[];
    // A: p*2560 : [128 m][20] (16 kpair + 4 pad)
    // B: 5120 + p*2176 : [16 kpair][136] (132+4 pad, stride 136%32==8)
    const uint32_t sbase = smem_u32(smu);
    const int tid = threadIdx.x;
    const int lane = tid & 31, w = tid >> 5;
    const int gid = lane >> 2, tidg = lane & 3;
    const int mbase = (w >> 2) * 64, nbase = (w & 3) * 32;
    const int r0 = blockIdx.y * 128, j0 = blockIdx.x * 128;

    float acc[4][4][4];
#pragma unroll
    for (int mt = 0; mt < 4; mt++)
#pragma unroll
        for (int nt = 0; nt < 4; nt++)
#pragma unroll
            for (int c = 0; c < 4; c++) acc[mt][nt][c] = 0.0f;

    auto issue = [&](int c) {
        int p = c & 1;
        uint32_t aA = sbase + (uint32_t)(p * 2560) * 4;
        uint32_t aB = sbase + (uint32_t)(5120 + p * 2176) * 4;
#pragma unroll
        for (int it = 0; it < 2; it++) {
            int f = tid + it * 256;           // 512 cp16: [128 m][4 k4]
            int m = f >> 2, k4 = f & 3;
            cp16(aA + (uint32_t)(m * 20 + k4 * 4) * 4,
                 g_IPk_hi + (size_t)(r0 + m) * 128 + c * 16 + k4 * 4);
        }
#pragma unroll
        for (int it = 0; it < 2; it++) {
            int f = tid + it * 256;           // 512 cp16: [16 kp][32 j4]
            int kp = f >> 5, j4 = f & 31;
            cp16(aB + (uint32_t)(kp * 136 + j4 * 4) * 4,
                 g_WihPk_hi + (size_t)(c * 16 + kp) * 768 + j0 + j4 * 4);
        }
        cp_commit();
    };

    issue(0);
    for (int c = 0; c < 8; c++) {
        if (c + 1 < 8) { issue(c + 1); cp_wait1(); } else { cp_wait0(); }
        __syncthreads();
        const uint32_t* Ah = smu + (c & 1) * 2560;
        const uint32_t* Bh = smu + 5120 + (c & 1) * 2176;
#pragma unroll
        for (int ks = 0; ks < 2; ks++) {
            const int kp0 = 8 * ks + tidg, kp1 = kp0 + 4;
            uint32_t bh[4][2];
#pragma unroll
            for (int nt = 0; nt < 4; nt++) {
                int j = nbase + 8 * nt + gid;
                bh[nt][0] = Bh[kp0 * 136 + j];
                bh[nt][1] = Bh[kp1 * 136 + j];
            }
#pragma unroll
            for (int mt = 0; mt < 4; mt++) {
                int row = mbase + 16 * mt + gid;
                uint32_t ah0 = Ah[row * 20 + kp0];
                uint32_t ah1 = Ah[(row + 8) * 20 + kp0];
                uint32_t ah2 = Ah[row * 20 + kp1];
                uint32_t ah3 = Ah[(row + 8) * 20 + kp1];
#pragma unroll
                for (int nt = 0; nt < 4; nt++)
                    mma16816(acc[mt][nt][0], acc[mt][nt][1], acc[mt][nt][2],
                             acc[mt][nt][3], ah0, ah1, ah2, ah3,
                             bh[nt][0], bh[nt][1]);
            }
        }
        __syncthreads();  // buffer reuse guard before next issue
    }

    // epilogue: add bias, store float2s
    const bool addh = (j0 + nbase) < 512;
    float2 bias[4];
#pragma unroll
    for (int nt = 0; nt < 4; nt++) {
        int j = j0 + nbase + 8 * nt + 2 * tidg;
        float2 v = *(const float2*)(b_ih + j);
        if (addh) {
            float2 h2 = *(const float2*)(b_hh + j);
            v.x += h2.x; v.y += h2.y;
        }
        bias[nt] = v;
    }
#pragma unroll
    for (int mt = 0; mt < 4; mt++)
#pragma unroll
        for (int rh = 0; rh < 2; rh++) {
            int row = mbase + 16 * mt + 8 * rh + gid;
            float* dst = g_GI + (size_t)(r0 + row) * 768 + j0 + nbase;
#pragma unroll
            for (int nt = 0; nt < 4; nt++) {
                float2 o;
                o.x = acc[mt][nt][2 * rh] + bias[nt].x;
                o.y = acc[mt][nt][2 * rh + 1] + bias[nt].y;
                *(float2*)(dst + 8 * nt + 2 * tidg) = o;
            }
        }
}

// ---------------------------------------------------------------------------
// RNN (= R8/R14, best measured 292us): one CTA per batch (128 CTAs, 512 thr).
// h in SMEM as f16x2 hi/lo; warp w owns d in [16w, 16w+16) for all 3 gates
// => epilogue fully in-warp. 2-term split: (h_hi + h_lo) @ fp16(W_hh).
// Weights staged per 16-kpair chunk (8 chunks/step) via cp.async,
// double-buffered; B fragments shared across the two h passes.
__global__ void __launch_bounds__(512) rnn_tc(const float* __restrict__ user_embs,
                                              const float* __restrict__ b_hh,
                                              const float* __restrict__ w_out,
                                              const float* __restrict__ b_out,
                                              const int* __restrict__ length,
                                              float* __restrict__ out) {
    extern __shared__ uint32_t smu[];
    uint32_t* hsm_hi = smu;            // [64][132] (128 kpair + 4 pad)
    uint32_t* hsm_lo = smu + 8448;
    // weight bufs @16896 + p*12416 : [16 kp][776]
    float* ysm = (float*)(smu + 41728);  // [64]
    const uint32_t sbase = smem_u32(smu);

    const int b = blockIdx.x;
    const int tid = threadIdx.x;
    const int lane = tid & 31, w = tid >> 5;
    const int gid = lane >> 2, tidg = lane & 3;
    const int dbase = w * 16;

    // h0 = user_embs[b, clip(len-1,0)] broadcast to 64 rows, split to f16 hi/lo
    int hidx = length[b] - 1;
    if (hidx < 0) hidx = 0;
    const float* u0 = user_embs + ((size_t)b * 64 + hidx) * 256;
    for (int i = tid; i < 64 * 128; i += 512) {
        int row = i >> 7, kp = i & 127;
        float2 v = *(const float2*)(u0 + 2 * kp);
        uint32_t lo, hi = split_h2(v.x, v.y, lo);
        hsm_hi[row * 132 + kp] = hi;
        hsm_lo[row * 132 + kp] = lo;
    }
    const float bout = b_out[0];
    if (tid < 64) ysm[tid] = bout;

    float2 bhn[2], wo[2];
#pragma unroll
    for (int nt = 0; nt < 2; nt++) {
        int d = dbase + 8 * nt + 2 * tidg;
        bhn[nt] = *(const float2*)(b_hh + 512 + d);
        wo[nt] = *(const float2*)(w_out + d);
    }

    auto issue = [&](int c) {
        int p = c & 1;
#pragma unroll
        for (int it = 0; it < 6; it++) {
            int f = tid + it * 512;        // 3072 cp16: [16 kk][192 j4]
            int kk = f / 192, j4 = f - kk * 192;
            cp16(sbase + (uint32_t)(16896 + p * 12416 + kk * 776 + j4 * 4) * 4,
                 g_WhhPk_hi + (size_t)(c * 16 + kk) * 768 + j4 * 4);
        }
        cp_commit();
    };

    float acc[4][3][2][4];

    for (int k = 0; k < 10; k++) {
        // prefetch this step's GI slab (64 rows x 768 floats) into L2
        {
            const float* gib = g_GI + ((size_t)(b * 64) * 10 + k) * 768;
            for (int i = tid; i < 1536; i += 512) {
                int r = i / 24, l = i - r * 24;
                prefetch_l2((const char*)(gib + (size_t)r * 7680) + l * 128);
            }
        }
#pragma unroll
        for (int mt = 0; mt < 4; mt++)
#pragma unroll
            for (int g = 0; g < 3; g++)
#pragma unroll
                for (int nt = 0; nt < 2; nt++)
#pragma unroll
                    for (int c = 0; c < 4; c++) acc[mt][g][nt][c] = 0.0f;

        issue(0);
        for (int c = 0; c < 8; c++) {
            if (c + 1 < 8) { issue(c + 1); cp_wait1(); } else { cp_wait0(); }
            __syncthreads();
            const uint32_t* wb = smu + 16896 + (c & 1) * 12416;
#pragma unroll
            for (int ks = 0; ks < 2; ks++) {
                // B fragments (w_hi), shared by both h passes
                uint32_t bfr[6][2];
#pragma unroll
                for (int g = 0; g < 3; g++)
#pragma unroll
                    for (int nt = 0; nt < 2; nt++) {
                        int n = g * 256 + dbase + 8 * nt + gid;
                        bfr[g * 2 + nt][0] = wb[(8 * ks + tidg) * 776 + n];
                        bfr[g * 2 + nt][1] = wb[(8 * ks + tidg + 4) * 776 + n];
                    }
                const int kpc = 16 * c + 8 * ks;
#pragma unroll
                for (int pass = 0; pass < 2; pass++) {
                    const uint32_t* hb = pass ? hsm_lo : hsm_hi;
#pragma unroll
                    for (int mt = 0; mt < 4; mt++) {
                        int row = 16 * mt + gid;
                        uint32_t a0 = hb[row * 132 + kpc + tidg];
                        uint32_t a1 = hb[(row + 8) * 132 + kpc + tidg];
                        uint32_t a2 = hb[row * 132 + kpc + 4 + tidg];
                        uint32_t a3 = hb[(row + 8) * 132 + kpc + 4 + tidg];
#pragma unroll
                        for (int g = 0; g < 3; g++)
#pragma unroll
                            for (int nt = 0; nt < 2; nt++)
                                mma16816(acc[mt][g][nt][0], acc[mt][g][nt][1],
                                         acc[mt][g][nt][2], acc[mt][g][nt][3],
                                         a0, a1, a2, a3,
                                         bfr[g * 2 + nt][0], bfr[g * 2 + nt][1]);
                    }
                }
            }
            __syncthreads();  // buffer reuse guard; last iter: pre-epilogue guard
        }

        // fused GRU epilogue (each (row,d) cell owned by exactly one thread)
#pragma unroll
        for (int mt = 0; mt < 4; mt++)
#pragma unroll
            for (int rh = 0; rh < 2; rh++) {
                int row = 16 * mt + 8 * rh + gid;
                const float* gi = g_GI + ((size_t)(b * 64 + row) * 10 + k) * 768;
                float yp = 0.0f;
#pragma unroll
                for (int nt = 0; nt < 2; nt++) {
                    int d = dbase + 8 * nt + 2 * tidg;
                    int kp = d >> 1;
                    float2 gr = *(const float2*)(gi + d);
                    float2 gz = *(const float2*)(gi + 256 + d);
                    float2 gn = *(const float2*)(gi + 512 + d);
                    uint32_t hh = hsm_hi[row * 132 + kp];
                    uint32_t hl = hsm_lo[row * 132 + kp];
                    float2 hhf = __half22float2(*reinterpret_cast<half2*>(&hh));
                    float2 hlf = __half22float2(*reinterpret_cast<half2*>(&hl));
                    float hox = hhf.x + hlf.x, hoy = hhf.y + hlf.y;
                    int c0 = rh * 2;
                    float r0v = fast_sig(gr.x + acc[mt][0][nt][c0]);
                    float r1v = fast_sig(gr.y + acc[mt][0][nt][c0 + 1]);
                    float z0v = fast_sig(gz.x + acc[mt][1][nt][c0]);
                    float z1v = fast_sig(gz.y + acc[mt][1][nt][c0 + 1]);
                    float hn0 = acc[mt][2][nt][c0] + bhn[nt].x;
                    float hn1 = acc[mt][2][nt][c0 + 1] + bhn[nt].y;
                    float n0 = fast_tanh(gn.x + r0v * hn0);
                    float n1 = fast_tanh(gn.y + r1v * hn1);
                    float h0n = (1.0f - z0v) * n0 + z0v * hox;
                    float h1n = (1.0f - z1v) * n1 + z1v * hoy;
                    uint32_t nlo, nhi = split_h2(h0n, h1n, nlo);
                    hsm_hi[row * 132 + kp] = nhi;
                    hsm_lo[row * 132 + kp] = nlo;
                    yp += h0n * wo[nt].x + h1n * wo[nt].y;
                }
                yp += __shfl_xor_sync(0xffffffffu, yp, 1);
                yp += __shfl_xor_sync(0xffffffffu, yp, 2);
                if (tidg == 0) atomicAdd(&ysm[row], yp);
            }
        __syncthreads();
        if (tid < 64) {
            out[((size_t)(b * 64) + tid) * 10 + k] = ysm[tid];
            ysm[tid] = bout;
        }
        __syncthreads();  // order out-write/ysm-reset + h writes before next step
    }
}

// ---------------------------------------------------------------------------
extern "C" void kernel_launch(void* const* d_in, const int* in_sizes, int n_in,
                              void* d_out, int out_size) {
    (void)in_sizes; (void)n_in; (void)out_size;
    const float* item_embs = (const float*)d_in[0];  // [128,64,10,256]
    const float* user_embs = (const float*)d_in[1];  // [128,64,256]
    const float* W_ih      = (const float*)d_in[2];  // [768,512]
    const float* W_hh      = (const float*)d_in[3];  // [768,256]
    const float* b_ih      = (const float*)d_in[4];  // [768]
    const float* b_hh      = (const float*)d_in[5];  // [768]
    const float* w_out     = (const float*)d_in[6];  // [256]
    const float* b_out     = (const float*)d_in[7];  // scalar
    const int*   length    = (const int*)d_in[8];    // [128]
    float* out = (float*)d_out;                      // [128,64,10]

    prep_weights<<<384, 256>>>(W_ih, W_hh);
    prep_items<<<10240, 256>>>(item_embs);

    const int gi_smem = 9472 * 4;  // 37888 B
    cudaFuncSetAttribute(gi_tc, cudaFuncAttributeMaxDynamicSharedMemorySize,
                         gi_smem);
    dim3 gg(6, 640);  // j-blocks inner => A-tile L2 reuse across 6 j-blocks
    gi_tc<<<gg, 256, gi_smem>>>(b_ih, b_hh);

    const int rnn_smem = 41792 * 4;  // 167168 B
    cudaFuncSetAttribute(rnn_tc, cudaFuncAttributeMaxDynamicSharedMemorySize,
                         rnn_smem);
    rnn_tc<<<128, 512, rnn_smem>>>(user_embs, b_hh, w_out, b_out, length, out);
}